// round 7
// baseline (speedup 1.0000x reference)
#include <cuda_runtime.h>
#include <cuda_fp16.h>
#include <math_constants.h>

#define NNODES 50000
#define EEDGES 800000
#define ETOT   (EEDGES + NNODES)
#define FIN    128
#define HC     128
#define NHEAD  2
#define NCLS   16
#define NEG    0.2f
#define WPB    8
#define GEMM_BLKS (2 * ((NNODES + 63) / 64))   // 1564
#define CNT_BLKS  ((ETOT + 255) / 256)         // 3321

// ---------------- scratch ----------------
__device__ __half g_hh[(size_t)NNODES * HC];   // 12.8 MB, gather source
__device__ float  g_asrc[NNODES * NHEAD];
__device__ float  g_adst[NNODES * NHEAD];
__device__ int    g_cnt[NNODES];
__device__ int    g_cur[NNODES];
__device__ int    g_off[NNODES];
__device__ int    g_csrc[ETOT];
__device__ float2 g_cw[ETOT];                  // per-edge softmax numerators (w0,w1)
__device__ int    g_es[ETOT];
__device__ int    g_ed[ETOT];
__device__ int    g_total;
__device__ int    g_idx64;

__device__ __forceinline__ void load_edge(const void* ei, int t, int& s, int& d) {
    if (t >= EEDGES) { s = d = t - EEDGES; return; }
    if (g_idx64) {
        const long long* p = (const long long*)ei;
        s = (int)p[t]; d = (int)p[EEDGES + t];
    } else {
        const int* p = (const int*)ei;
        s = p[t]; d = p[EEDGES + t];
    }
}

// ---------------- init ------------------------------------------------------
__global__ void k_init(const void* ei) {
    int i = blockIdx.x * blockDim.x + threadIdx.x;
    if (i < NNODES) { g_cnt[i] = 0; g_cur[i] = 0; }
    if (i == 0) g_total = 0;
    if (blockIdx.x == 0 && threadIdx.x < 32) {
        const long long* p = (const long long*)ei;
        int ok = 1;
        #pragma unroll
        for (int r = 0; r < 8; r++) {
            long long v = p[threadIdx.x + r * 32];
            if (v < 0 || v >= NNODES) ok = 0;
        }
        ok = __all_sync(0xffffffffu, ok);
        if (threadIdx.x == 0) g_idx64 = ok;
    }
}

// ---------------- fused: [h = x@W + att epilogue] || [edge count/decode] ----
__global__ void k_gemm_count(const float* __restrict__ x, const float* __restrict__ W,
                             const float* __restrict__ att_src, const float* __restrict__ att_dst,
                             const void* __restrict__ ei) {
    __shared__ float xs[64][32];
    __shared__ float ws[32][64];
    int tid = threadIdx.x;

    if (blockIdx.x >= GEMM_BLKS) {
        int t = (blockIdx.x - GEMM_BLKS) * 256 + tid;
        if (t < ETOT) {
            int s, d; load_edge(ei, t, s, d);
            g_es[t] = s; g_ed[t] = d;
            atomicAdd(&g_cnt[d], 1);
        }
        return;
    }

    int head = blockIdx.x & 1;
    int col0 = head * 64;
    int row0 = (blockIdx.x >> 1) * 64;
    int ty = tid >> 4, tx = tid & 15;
    float acc[4][4] = {};

    for (int kt = 0; kt < FIN; kt += 32) {
        #pragma unroll
        for (int i = 0; i < 2; i++) {
            int lin = tid + i * 256;
            int r = lin >> 3, kk = (lin & 7) << 2;
            int gr = row0 + r;
            float4 v = make_float4(0.f, 0.f, 0.f, 0.f);
            if (gr < NNODES) v = *(const float4*)&x[(size_t)gr * FIN + kt + kk];
            xs[r][kk] = v.x; xs[r][kk + 1] = v.y; xs[r][kk + 2] = v.z; xs[r][kk + 3] = v.w;
        }
        #pragma unroll
        for (int i = 0; i < 2; i++) {
            int lin = tid + i * 256;
            int k = lin >> 4, cc = (lin & 15) << 2;
            float4 v = *(const float4*)&W[(size_t)(kt + k) * HC + col0 + cc];
            ws[k][cc] = v.x; ws[k][cc + 1] = v.y; ws[k][cc + 2] = v.z; ws[k][cc + 3] = v.w;
        }
        __syncthreads();
        #pragma unroll
        for (int k = 0; k < 32; k++) {
            float a[4], b[4];
            #pragma unroll
            for (int i = 0; i < 4; i++) a[i] = xs[ty * 4 + i][k];
            #pragma unroll
            for (int j = 0; j < 4; j++) b[j] = ws[k][tx * 4 + j];
            #pragma unroll
            for (int i = 0; i < 4; i++)
                #pragma unroll
                for (int j = 0; j < 4; j++)
                    acc[i][j] += a[i] * b[j];
        }
        __syncthreads();
    }

    float asv[4], adv[4];
    #pragma unroll
    for (int j = 0; j < 4; j++) {
        asv[j] = att_src[col0 + tx * 4 + j];
        adv[j] = att_dst[col0 + tx * 4 + j];
    }

    float ps[4], pd[4];
    #pragma unroll
    for (int i = 0; i < 4; i++) {
        int gr = row0 + ty * 4 + i;
        ps[i] = acc[i][0] * asv[0] + acc[i][1] * asv[1] + acc[i][2] * asv[2] + acc[i][3] * asv[3];
        pd[i] = acc[i][0] * adv[0] + acc[i][1] * adv[1] + acc[i][2] * adv[2] + acc[i][3] * adv[3];
        if (gr < NNODES) {
            __half2 p0 = __float22half2_rn(make_float2(acc[i][0], acc[i][1]));
            __half2 p1 = __float22half2_rn(make_float2(acc[i][2], acc[i][3]));
            uint2 pk = make_uint2(*(unsigned*)&p0, *(unsigned*)&p1);
            *(uint2*)&g_hh[(size_t)gr * HC + col0 + tx * 4] = pk;
        }
    }
    #pragma unroll
    for (int o = 8; o; o >>= 1) {
        #pragma unroll
        for (int i = 0; i < 4; i++) {
            ps[i] += __shfl_xor_sync(0xffffffffu, ps[i], o);
            pd[i] += __shfl_xor_sync(0xffffffffu, pd[i], o);
        }
    }
    if (tx == 0) {
        #pragma unroll
        for (int i = 0; i < 4; i++) {
            int gr = row0 + ty * 4 + i;
            if (gr < NNODES) {
                g_asrc[gr * 2 + head] = ps[i];
                g_adst[gr * 2 + head] = pd[i];
            }
        }
    }
}

// ---------------- warp-aggregated bucket allocation -------------------------
__global__ void k_alloc() {
    int i = blockIdx.x * blockDim.x + threadIdx.x;
    int lane = threadIdx.x & 31;
    int cnt = (i < NNODES) ? g_cnt[i] : 0;
    int pre = cnt;
    #pragma unroll
    for (int o = 1; o < 32; o <<= 1) {
        int v = __shfl_up_sync(0xffffffffu, pre, o);
        if (lane >= o) pre += v;
    }
    int tot = __shfl_sync(0xffffffffu, pre, 31);
    int base = 0;
    if (lane == 31) base = atomicAdd(&g_total, tot);
    base = __shfl_sync(0xffffffffu, base, 31);
    if (i < NNODES) g_off[i] = base + pre - cnt;
}

// ---------------- fill: scatter src + precomputed softmax numerators --------
__global__ void k_fill() {
    int t = blockIdx.x * blockDim.x + threadIdx.x;
    if (t >= ETOT) return;
    int s = g_es[t], d = g_ed[t];
    float2 as = *(const float2*)&g_asrc[s * 2];
    float2 ad = *(const float2*)&g_adst[d * 2];
    float e0 = as.x + ad.x, e1 = as.y + ad.y;
    e0 = e0 > 0.f ? e0 : NEG * e0;
    e1 = e1 > 0.f ? e1 : NEG * e1;
    int pos = g_off[d] + atomicAdd(&g_cur[d], 1);
    g_csrc[pos] = s;
    g_cw[pos] = make_float2(__expf(e0), __expf(e1));
}

// ---------------- fused softmax-aggregate + bias/relu/fc/log_softmax --------
// Lane layout: half = lane>>4 (edge-slot parity), csub = lane&15 (channel
// group: 8 channels each; csub 0-7 -> head0, 8-15 -> head1).
__global__ void k_agg(const float* __restrict__ bias, const float* __restrict__ Wfc,
                      const float* __restrict__ bfc, float* __restrict__ out) {
    __shared__ float wt[NCLS * HC];
    __shared__ int   sh_s[WPB][32];
    __shared__ float sh_w0[WPB][32];
    __shared__ float sh_w1[WPB][32];
    int tid = threadIdx.x;
    for (int i = tid; i < NCLS * HC; i += blockDim.x) {
        int c = i >> 7, k = i & 127;
        wt[i] = Wfc[k * NCLS + c];
    }
    __syncthreads();

    int wid = tid >> 5, lane = tid & 31;
    int node = blockIdx.x * WPB + wid;
    if (node >= NNODES) return;

    int off = g_off[node];
    int deg = g_cnt[node];
    int half = lane >> 4;
    int csub = lane & 15;
    int head = csub >> 3;

    float acc[8] = {};
    float den0 = 0.f, den1 = 0.f;

    for (int base = 0; base < deg; base += 32) {
        int i = base + lane;
        int s = 0; float2 cw = make_float2(0.f, 0.f);
        if (i < deg) {
            s = g_csrc[off + i];
            cw = g_cw[off + i];
        }
        sh_s[wid][lane] = s; sh_w0[wid][lane] = cw.x; sh_w1[wid][lane] = cw.y;
        den0 += cw.x; den1 += cw.y;
        __syncwarp();

        int nthis = deg - base; if (nthis > 32) nthis = 32;
        int nproc = (nthis + 7) & ~7;            // pad to 8; padded have w=0,s=0
        for (int j = 0; j < nproc; j += 8) {
            #pragma unroll
            for (int p = 0; p < 4; p++) {
                int e = j + p * 2 + half;
                int s_e = sh_s[wid][e];
                float w = head ? sh_w1[wid][e] : sh_w0[wid][e];
                uint4 r = *(const uint4*)&g_hh[(size_t)s_e * HC + csub * 8];
                float2 f0 = __half22float2(*(__half2*)&r.x);
                float2 f1 = __half22float2(*(__half2*)&r.y);
                float2 f2 = __half22float2(*(__half2*)&r.z);
                float2 f3 = __half22float2(*(__half2*)&r.w);
                acc[0] += f0.x * w; acc[1] += f0.y * w;
                acc[2] += f1.x * w; acc[3] += f1.y * w;
                acc[4] += f2.x * w; acc[5] += f2.y * w;
                acc[6] += f3.x * w; acc[7] += f3.y * w;
            }
        }
        __syncwarp();
    }

    // merge the two edge-slot halves (lane k and k+16 own same channels)
    #pragma unroll
    for (int k = 0; k < 8; k++) acc[k] += __shfl_xor_sync(0xffffffffu, acc[k], 16);
    // dens: every lane staged distinct edges -> full-warp reduce
    #pragma unroll
    for (int o = 16; o; o >>= 1) {
        den0 += __shfl_xor_sync(0xffffffffu, den0, o);
        den1 += __shfl_xor_sync(0xffffffffu, den1, o);
    }

    float inv = 1.f / ((head ? den1 : den0) + 1e-16f);
    float4 b0 = *(const float4*)&bias[csub * 8];
    float4 b1 = *(const float4*)&bias[csub * 8 + 4];
    float v[8];
    v[0] = fmaxf(acc[0] * inv + b0.x, 0.f); v[1] = fmaxf(acc[1] * inv + b0.y, 0.f);
    v[2] = fmaxf(acc[2] * inv + b0.z, 0.f); v[3] = fmaxf(acc[3] * inv + b0.w, 0.f);
    v[4] = fmaxf(acc[4] * inv + b1.x, 0.f); v[5] = fmaxf(acc[5] * inv + b1.y, 0.f);
    v[6] = fmaxf(acc[6] * inv + b1.z, 0.f); v[7] = fmaxf(acc[7] * inv + b1.w, 0.f);

    // fc 128->16: each lane contributes its 8 channels; reduce within 16-lane group
    float fa[NCLS];
    int k0 = csub * 8;
    #pragma unroll
    for (int c = 0; c < NCLS; c++) {
        const float* wr = &wt[c * HC + k0];
        float t0 = v[0] * wr[0] + v[1] * wr[1] + v[2] * wr[2] + v[3] * wr[3];
        float t1 = v[4] * wr[4] + v[5] * wr[5] + v[6] * wr[6] + v[7] * wr[7];
        fa[c] = t0 + t1;
    }
    #pragma unroll
    for (int c = 0; c < NCLS; c++)
        #pragma unroll
        for (int o = 8; o; o >>= 1) fa[c] += __shfl_xor_sync(0xffffffffu, fa[c], o);

    if (lane == 0) {
        float mx = -CUDART_INF_F;
        #pragma unroll
        for (int c = 0; c < NCLS; c++) { fa[c] += bfc[c]; mx = fmaxf(mx, fa[c]); }
        float se = 0.f;
        #pragma unroll
        for (int c = 0; c < NCLS; c++) se += __expf(fa[c] - mx);
        float lse = mx + logf(se);
        #pragma unroll
        for (int c = 0; c < NCLS; c++) out[(size_t)node * NCLS + c] = fa[c] - lse;
    }
}

// ---------------- launch ----------------------------------------------------
extern "C" void kernel_launch(void* const* d_in, const int* in_sizes, int n_in,
                              void* d_out, int out_size) {
    const float* x       = (const float*)d_in[0];
    const void*  ei      = d_in[1];
    const float* W       = (const float*)d_in[2];
    const float* att_src = (const float*)d_in[3];
    const float* att_dst = (const float*)d_in[4];
    const float* bias    = (const float*)d_in[5];
    const float* Wfc     = (const float*)d_in[6];
    const float* bfc     = (const float*)d_in[7];
    float* out = (float*)d_out;

    k_init<<<(NNODES + 255) / 256, 256>>>(ei);
    k_gemm_count<<<GEMM_BLKS + CNT_BLKS, 256>>>(x, W, att_src, att_dst, ei);
    k_alloc<<<(NNODES + 255) / 256, 256>>>();
    k_fill<<<(ETOT + 255) / 256, 256>>>();
    k_agg<<<(NNODES + WPB - 1) / WPB, 256>>>(bias, Wfc, bfc, out);
}

// round 8
// speedup vs baseline: 1.2666x; 1.2666x over previous
#include <cuda_runtime.h>
#include <cuda_fp16.h>
#include <math_constants.h>

#define NNODES 50000
#define EEDGES 800000
#define ETOT   (EEDGES + NNODES)
#define FIN    128
#define HC     128
#define NHEAD  2
#define NCLS   16
#define NEG    0.2f
#define WPB    8
#define GEMM_BLKS (2 * ((NNODES + 63) / 64))   // 1564
#define CNT_BLKS  ((ETOT + 255) / 256)         // 3321
#define EHALF  ((ETOT + 1) / 2)

// ---------------- scratch ----------------
__device__ __half g_hh[(size_t)NNODES * HC];   // 12.8 MB, gather source
__device__ float  g_asrc[NNODES * NHEAD];
__device__ float  g_adst[NNODES * NHEAD];
__device__ int    g_cnt[NNODES];
__device__ int    g_cur[NNODES];
__device__ int    g_off[NNODES];
__device__ int    g_csrc[ETOT];
__device__ int    g_es[ETOT];
__device__ int    g_ed[ETOT];
__device__ int    g_total;
__device__ int    g_idx64;

__device__ __forceinline__ void load_edge(const void* ei, int t, int& s, int& d) {
    if (t >= EEDGES) { s = d = t - EEDGES; return; }
    if (g_idx64) {
        const long long* p = (const long long*)ei;
        s = (int)p[t]; d = (int)p[EEDGES + t];
    } else {
        const int* p = (const int*)ei;
        s = p[t]; d = p[EEDGES + t];
    }
}

// ---------------- init ------------------------------------------------------
__global__ void k_init(const void* ei) {
    int i = blockIdx.x * blockDim.x + threadIdx.x;
    if (i < NNODES) { g_cnt[i] = 0; g_cur[i] = 0; }
    if (i == 0) g_total = 0;
    if (blockIdx.x == 0 && threadIdx.x < 32) {
        const long long* p = (const long long*)ei;
        int ok = 1;
        #pragma unroll
        for (int r = 0; r < 8; r++) {
            long long v = p[threadIdx.x + r * 32];
            if (v < 0 || v >= NNODES) ok = 0;
        }
        ok = __all_sync(0xffffffffu, ok);
        if (threadIdx.x == 0) g_idx64 = ok;
    }
}

// ---------------- fused: [h = x@W + att epilogue] || [edge count/decode] ----
__global__ void k_gemm_count(const float* __restrict__ x, const float* __restrict__ W,
                             const float* __restrict__ att_src, const float* __restrict__ att_dst,
                             const void* __restrict__ ei) {
    __shared__ float xs[64][32];
    __shared__ float ws[32][64];
    int tid = threadIdx.x;

    if (blockIdx.x >= GEMM_BLKS) {
        int t = (blockIdx.x - GEMM_BLKS) * 256 + tid;
        if (t < ETOT) {
            int s, d; load_edge(ei, t, s, d);
            g_es[t] = s; g_ed[t] = d;
            atomicAdd(&g_cnt[d], 1);
        }
        return;
    }

    int head = blockIdx.x & 1;
    int col0 = head * 64;
    int row0 = (blockIdx.x >> 1) * 64;
    int ty = tid >> 4, tx = tid & 15;
    float acc[4][4] = {};

    for (int kt = 0; kt < FIN; kt += 32) {
        #pragma unroll
        for (int i = 0; i < 2; i++) {
            int lin = tid + i * 256;
            int r = lin >> 3, kk = (lin & 7) << 2;
            int gr = row0 + r;
            float4 v = make_float4(0.f, 0.f, 0.f, 0.f);
            if (gr < NNODES) v = *(const float4*)&x[(size_t)gr * FIN + kt + kk];
            xs[r][kk] = v.x; xs[r][kk + 1] = v.y; xs[r][kk + 2] = v.z; xs[r][kk + 3] = v.w;
        }
        #pragma unroll
        for (int i = 0; i < 2; i++) {
            int lin = tid + i * 256;
            int k = lin >> 4, cc = (lin & 15) << 2;
            float4 v = *(const float4*)&W[(size_t)(kt + k) * HC + col0 + cc];
            ws[k][cc] = v.x; ws[k][cc + 1] = v.y; ws[k][cc + 2] = v.z; ws[k][cc + 3] = v.w;
        }
        __syncthreads();
        #pragma unroll
        for (int k = 0; k < 32; k++) {
            float a[4], b[4];
            #pragma unroll
            for (int i = 0; i < 4; i++) a[i] = xs[ty * 4 + i][k];
            #pragma unroll
            for (int j = 0; j < 4; j++) b[j] = ws[k][tx * 4 + j];
            #pragma unroll
            for (int i = 0; i < 4; i++)
                #pragma unroll
                for (int j = 0; j < 4; j++)
                    acc[i][j] += a[i] * b[j];
        }
        __syncthreads();
    }

    float asv[4], adv[4];
    #pragma unroll
    for (int j = 0; j < 4; j++) {
        asv[j] = att_src[col0 + tx * 4 + j];
        adv[j] = att_dst[col0 + tx * 4 + j];
    }

    float ps[4], pd[4];
    #pragma unroll
    for (int i = 0; i < 4; i++) {
        int gr = row0 + ty * 4 + i;
        ps[i] = acc[i][0] * asv[0] + acc[i][1] * asv[1] + acc[i][2] * asv[2] + acc[i][3] * asv[3];
        pd[i] = acc[i][0] * adv[0] + acc[i][1] * adv[1] + acc[i][2] * adv[2] + acc[i][3] * adv[3];
        if (gr < NNODES) {
            __half2 p0 = __float22half2_rn(make_float2(acc[i][0], acc[i][1]));
            __half2 p1 = __float22half2_rn(make_float2(acc[i][2], acc[i][3]));
            uint2 pk = make_uint2(*(unsigned*)&p0, *(unsigned*)&p1);
            *(uint2*)&g_hh[(size_t)gr * HC + col0 + tx * 4] = pk;
        }
    }
    #pragma unroll
    for (int o = 8; o; o >>= 1) {
        #pragma unroll
        for (int i = 0; i < 4; i++) {
            ps[i] += __shfl_xor_sync(0xffffffffu, ps[i], o);
            pd[i] += __shfl_xor_sync(0xffffffffu, pd[i], o);
        }
    }
    if (tx == 0) {
        #pragma unroll
        for (int i = 0; i < 4; i++) {
            int gr = row0 + ty * 4 + i;
            if (gr < NNODES) {
                g_asrc[gr * 2 + head] = ps[i];
                g_adst[gr * 2 + head] = pd[i];
            }
        }
    }
}

// ---------------- warp-aggregated bucket allocation -------------------------
__global__ void k_alloc() {
    int i = blockIdx.x * blockDim.x + threadIdx.x;
    int lane = threadIdx.x & 31;
    int cnt = (i < NNODES) ? g_cnt[i] : 0;
    int pre = cnt;
    #pragma unroll
    for (int o = 1; o < 32; o <<= 1) {
        int v = __shfl_up_sync(0xffffffffu, pre, o);
        if (lane >= o) pre += v;
    }
    int tot = __shfl_sync(0xffffffffu, pre, 31);
    int base = 0;
    if (lane == 31) base = atomicAdd(&g_total, tot);
    base = __shfl_sync(0xffffffffu, base, 31);
    if (i < NNODES) g_off[i] = base + pre - cnt;
}

// ---------------- fill: 2 independent edges per thread (overlap atomics) ----
__global__ void k_fill() {
    int t = blockIdx.x * blockDim.x + threadIdx.x;
    if (t >= EHALF) return;
    int t2 = t + EHALF;
    int s1 = g_es[t], d1 = g_ed[t];
    int s2 = 0, d2 = 0;
    bool has2 = (t2 < ETOT);
    if (has2) { s2 = g_es[t2]; d2 = g_ed[t2]; }
    int pos1 = g_off[d1] + atomicAdd(&g_cur[d1], 1);
    int pos2 = 0;
    if (has2) pos2 = g_off[d2] + atomicAdd(&g_cur[d2], 1);
    g_csrc[pos1] = s1;
    if (has2) g_csrc[pos2] = s2;
}

// ---------------- fused softmax-aggregate + bias/relu/fc/log_softmax --------
__global__ void k_agg(const float* __restrict__ bias, const float* __restrict__ Wfc,
                      const float* __restrict__ bfc, float* __restrict__ out) {
    __shared__ float wt[NCLS * HC];
    __shared__ int   sh_s[WPB][32];
    __shared__ float sh_w0[WPB][32];
    __shared__ float sh_w1[WPB][32];
    int tid = threadIdx.x;
    for (int i = tid; i < NCLS * HC; i += blockDim.x) {
        int c = i >> 7, k = i & 127;
        wt[i] = Wfc[k * NCLS + c];
    }
    __syncthreads();

    int wid = tid >> 5, lane = tid & 31;
    int node = blockIdx.x * WPB + wid;
    if (node >= NNODES) return;

    int off = g_off[node];
    int deg = g_cnt[node];
    float ad0 = g_adst[node * 2], ad1 = g_adst[node * 2 + 1];
    int head = lane >> 4;

    float acc0 = 0.f, acc1 = 0.f, acc2 = 0.f, acc3 = 0.f, den = 0.f;

    for (int base = 0; base < deg; base += 32) {
        int i = base + lane;
        int s = 0; float w0 = 0.f, w1 = 0.f;
        if (i < deg) {
            s = g_csrc[off + i];
            float2 as = *(const float2*)&g_asrc[s * 2];
            float e0 = as.x + ad0, e1 = as.y + ad1;
            e0 = e0 > 0.f ? e0 : NEG * e0;
            e1 = e1 > 0.f ? e1 : NEG * e1;
            w0 = __expf(e0); w1 = __expf(e1);
        }
        sh_s[wid][lane] = s; sh_w0[wid][lane] = w0; sh_w1[wid][lane] = w1;
        __syncwarp();

        int nthis = deg - base; if (nthis > 32) nthis = 32;
        int nproc = (nthis + 7) & ~7;          // pad to 8; padded lanes have w=0,s=0
        const float* whp = head ? sh_w1[wid] : sh_w0[wid];
        for (int j = 0; j < nproc; j += 8) {
            int se[8]; float we[8];
            #pragma unroll
            for (int p = 0; p < 8; p++) { se[p] = sh_s[wid][j + p]; we[p] = whp[j + p]; }
            uint2 r[8];
            #pragma unroll
            for (int p = 0; p < 8; p++)
                r[p] = *(const uint2*)&g_hh[(size_t)se[p] * HC + lane * 4];
            #pragma unroll
            for (int p = 0; p < 8; p++) {
                float2 f01 = __half22float2(*(__half2*)&r[p].x);
                float2 f23 = __half22float2(*(__half2*)&r[p].y);
                den  += we[p];
                acc0 += f01.x * we[p]; acc1 += f01.y * we[p];
                acc2 += f23.x * we[p]; acc3 += f23.y * we[p];
            }
        }
        __syncwarp();
    }

    float inv = 1.f / (den + 1e-16f);
    float4 bv = *(const float4*)&bias[lane * 4];
    float v0 = fmaxf(acc0 * inv + bv.x, 0.f);
    float v1 = fmaxf(acc1 * inv + bv.y, 0.f);
    float v2 = fmaxf(acc2 * inv + bv.z, 0.f);
    float v3 = fmaxf(acc3 * inv + bv.w, 0.f);

    float fa[NCLS];
    int k0 = lane * 4;
    #pragma unroll
    for (int c = 0; c < NCLS; c++) {
        const float* wr = &wt[c * HC + k0];
        fa[c] = v0 * wr[0] + v1 * wr[1] + v2 * wr[2] + v3 * wr[3];
    }
    #pragma unroll
    for (int c = 0; c < NCLS; c++)
        #pragma unroll
        for (int o = 16; o; o >>= 1) fa[c] += __shfl_xor_sync(0xffffffffu, fa[c], o);

    if (lane == 0) {
        float mx = -CUDART_INF_F;
        #pragma unroll
        for (int c = 0; c < NCLS; c++) { fa[c] += bfc[c]; mx = fmaxf(mx, fa[c]); }
        float se = 0.f;
        #pragma unroll
        for (int c = 0; c < NCLS; c++) se += __expf(fa[c] - mx);
        float lse = mx + logf(se);
        #pragma unroll
        for (int c = 0; c < NCLS; c++) out[(size_t)node * NCLS + c] = fa[c] - lse;
    }
}

// ---------------- launch ----------------------------------------------------
extern "C" void kernel_launch(void* const* d_in, const int* in_sizes, int n_in,
                              void* d_out, int out_size) {
    const float* x       = (const float*)d_in[0];
    const void*  ei      = d_in[1];
    const float* W       = (const float*)d_in[2];
    const float* att_src = (const float*)d_in[3];
    const float* att_dst = (const float*)d_in[4];
    const float* bias    = (const float*)d_in[5];
    const float* Wfc     = (const float*)d_in[6];
    const float* bfc     = (const float*)d_in[7];
    float* out = (float*)d_out;

    k_init<<<(NNODES + 255) / 256, 256>>>(ei);
    k_gemm_count<<<GEMM_BLKS + CNT_BLKS, 256>>>(x, W, att_src, att_dst, ei);
    k_alloc<<<(NNODES + 255) / 256, 256>>>();
    k_fill<<<(EHALF + 255) / 256, 256>>>();
    k_agg<<<(NNODES + WPB - 1) / WPB, 256>>>(bias, Wfc, bfc, out);
}

// round 9
// speedup vs baseline: 1.2805x; 1.0109x over previous
#include <cuda_runtime.h>
#include <cuda_fp16.h>
#include <math_constants.h>

#define NNODES 50000
#define EEDGES 800000
#define ETOT   (EEDGES + NNODES)
#define FIN    128
#define HC     128
#define NHEAD  2
#define NCLS   16
#define NEG    0.2f
#define WPB    8
#define BM     128
#define BK     32
#define GEMM_BLKS (2 * ((NNODES + BM - 1) / BM))   // 782
#define CNT_BLKS  ((ETOT + 255) / 256)             // 3321

// ---------------- scratch ----------------
__device__ __half g_hh[(size_t)NNODES * HC];   // 12.8 MB, gather source
__device__ float  g_asrc[NNODES * NHEAD];
__device__ float  g_adst[NNODES * NHEAD];
__device__ int    g_cnt[NNODES];
__device__ int    g_off[NNODES];
__device__ int    g_csrc[ETOT];
__device__ int    g_es[ETOT];
__device__ int    g_ed[ETOT];
__device__ int    g_rank[ETOT];                // within-bucket rank from count pass
__device__ int    g_total;
__device__ int    g_idx64;

__device__ __forceinline__ void load_edge(const void* ei, int t, int& s, int& d) {
    if (t >= EEDGES) { s = d = t - EEDGES; return; }
    if (g_idx64) {
        const long long* p = (const long long*)ei;
        s = (int)p[t]; d = (int)p[EEDGES + t];
    } else {
        const int* p = (const int*)ei;
        s = p[t]; d = p[EEDGES + t];
    }
}

// ---------------- init ------------------------------------------------------
__global__ void k_init(const void* ei) {
    int i = blockIdx.x * blockDim.x + threadIdx.x;
    if (i < NNODES) g_cnt[i] = 0;
    if (i == 0) g_total = 0;
    if (blockIdx.x == 0 && threadIdx.x < 32) {
        const long long* p = (const long long*)ei;
        int ok = 1;
        #pragma unroll
        for (int r = 0; r < 8; r++) {
            long long v = p[threadIdx.x + r * 32];
            if (v < 0 || v >= NNODES) ok = 0;
        }
        ok = __all_sync(0xffffffffu, ok);
        if (threadIdx.x == 0) g_idx64 = ok;
    }
}

// ---------------- fused: [h = x@W + att epilogue] || [edge count/decode] ----
// GEMM: 128x64 block tile (BN=64 == one head), 256 threads, 8x4 micro-tile.
__global__ void __launch_bounds__(256, 2)
k_gemm_count(const float* __restrict__ x, const float* __restrict__ W,
             const float* __restrict__ att_src, const float* __restrict__ att_dst,
             const void* __restrict__ ei) {
    __shared__ float xs[BM][BK + 4];   // row-major, +4 pad: float4-aligned rows
    __shared__ float ws[BK][64];
    int tid = threadIdx.x;

    if (blockIdx.x >= GEMM_BLKS) {
        // ---- edge count + decode + rank ----
        int t = (blockIdx.x - GEMM_BLKS) * 256 + tid;
        if (t < ETOT) {
            int s, d; load_edge(ei, t, s, d);
            g_es[t] = s; g_ed[t] = d;
            g_rank[t] = atomicAdd(&g_cnt[d], 1);
        }
        return;
    }

    int head = blockIdx.x & 1;
    int col0 = head * 64;
    int row0 = (blockIdx.x >> 1) * BM;
    int ty = tid >> 4, tx = tid & 15;    // ty: 8-row group, tx: 4-col group
    float acc[8][4] = {};

    for (int kt = 0; kt < FIN; kt += BK) {
        // x tile: 128 rows x 32 ks = 1024 float4
        #pragma unroll
        for (int it = 0; it < 4; it++) {
            int lin = tid + it * 256;
            int r = lin >> 3, kk4 = (lin & 7) << 2;
            int gr = row0 + r;
            float4 v = make_float4(0.f, 0.f, 0.f, 0.f);
            if (gr < NNODES) v = *(const float4*)&x[(size_t)gr * FIN + kt + kk4];
            *(float4*)&xs[r][kk4] = v;
        }
        // W tile: 32 ks x 64 cols = 512 float4
        #pragma unroll
        for (int it = 0; it < 2; it++) {
            int lin = tid + it * 256;
            int k = lin >> 4, cc4 = (lin & 15) << 2;
            *(float4*)&ws[k][cc4] = *(const float4*)&W[(size_t)(kt + k) * HC + col0 + cc4];
        }
        __syncthreads();

        #pragma unroll
        for (int k4 = 0; k4 < BK / 4; k4++) {
            float4 b0 = *(const float4*)&ws[k4 * 4 + 0][tx * 4];
            float4 b1 = *(const float4*)&ws[k4 * 4 + 1][tx * 4];
            float4 b2 = *(const float4*)&ws[k4 * 4 + 2][tx * 4];
            float4 b3 = *(const float4*)&ws[k4 * 4 + 3][tx * 4];
            #pragma unroll
            for (int i = 0; i < 8; i++) {
                float4 a = *(const float4*)&xs[ty * 8 + i][k4 * 4];
                acc[i][0] += a.x * b0.x + a.y * b1.x + a.z * b2.x + a.w * b3.x;
                acc[i][1] += a.x * b0.y + a.y * b1.y + a.z * b2.y + a.w * b3.y;
                acc[i][2] += a.x * b0.z + a.y * b1.z + a.z * b2.z + a.w * b3.z;
                acc[i][3] += a.x * b0.w + a.y * b1.w + a.z * b2.w + a.w * b3.w;
            }
        }
        __syncthreads();
    }

    float asv[4], adv[4];
    #pragma unroll
    for (int j = 0; j < 4; j++) {
        asv[j] = att_src[col0 + tx * 4 + j];
        adv[j] = att_dst[col0 + tx * 4 + j];
    }

    #pragma unroll
    for (int i = 0; i < 8; i++) {
        int gr = row0 + ty * 8 + i;
        float ps = acc[i][0] * asv[0] + acc[i][1] * asv[1] + acc[i][2] * asv[2] + acc[i][3] * asv[3];
        float pd = acc[i][0] * adv[0] + acc[i][1] * adv[1] + acc[i][2] * adv[2] + acc[i][3] * adv[3];
        #pragma unroll
        for (int o = 8; o; o >>= 1) {      // reduce across the 16 tx lanes
            ps += __shfl_xor_sync(0xffffffffu, ps, o);
            pd += __shfl_xor_sync(0xffffffffu, pd, o);
        }
        if (gr < NNODES) {
            __half2 p0 = __float22half2_rn(make_float2(acc[i][0], acc[i][1]));
            __half2 p1 = __float22half2_rn(make_float2(acc[i][2], acc[i][3]));
            uint2 pk = make_uint2(*(unsigned*)&p0, *(unsigned*)&p1);
            *(uint2*)&g_hh[(size_t)gr * HC + col0 + tx * 4] = pk;
            if (tx == 0) {
                g_asrc[gr * 2 + head] = ps;
                g_adst[gr * 2 + head] = pd;
            }
        }
    }
}

// ---------------- warp-aggregated bucket allocation -------------------------
__global__ void k_alloc() {
    int i = blockIdx.x * blockDim.x + threadIdx.x;
    int lane = threadIdx.x & 31;
    int cnt = (i < NNODES) ? g_cnt[i] : 0;
    int pre = cnt;
    #pragma unroll
    for (int o = 1; o < 32; o <<= 1) {
        int v = __shfl_up_sync(0xffffffffu, pre, o);
        if (lane >= o) pre += v;
    }
    int tot = __shfl_sync(0xffffffffu, pre, 31);
    int base = 0;
    if (lane == 31) base = atomicAdd(&g_total, tot);
    base = __shfl_sync(0xffffffffu, base, 31);
    if (i < NNODES) g_off[i] = base + pre - cnt;
}

// ---------------- fill: atomic-free via precomputed rank --------------------
__global__ void k_fill() {
    int t = blockIdx.x * blockDim.x + threadIdx.x;
    if (t >= ETOT) return;
    int d = g_ed[t];
    g_csrc[g_off[d] + g_rank[t]] = g_es[t];
}

// ---------------- fused softmax-aggregate + bias/relu/fc/log_softmax --------
__global__ void k_agg(const float* __restrict__ bias, const float* __restrict__ Wfc,
                      const float* __restrict__ bfc, float* __restrict__ out) {
    __shared__ float wt[NCLS * HC];
    __shared__ int   sh_s[WPB][32];
    __shared__ float sh_w0[WPB][32];
    __shared__ float sh_w1[WPB][32];
    int tid = threadIdx.x;
    for (int i = tid; i < NCLS * HC; i += blockDim.x) {
        int c = i >> 7, k = i & 127;
        wt[i] = Wfc[k * NCLS + c];
    }
    __syncthreads();

    int wid = tid >> 5, lane = tid & 31;
    int node = blockIdx.x * WPB + wid;
    if (node >= NNODES) return;

    int off = g_off[node];
    int deg = g_cnt[node];
    float ad0 = g_adst[node * 2], ad1 = g_adst[node * 2 + 1];
    int head = lane >> 4;

    float acc0 = 0.f, acc1 = 0.f, acc2 = 0.f, acc3 = 0.f, den = 0.f;

    for (int base = 0; base < deg; base += 32) {
        int i = base + lane;
        int s = 0; float w0 = 0.f, w1 = 0.f;
        if (i < deg) {
            s = g_csrc[off + i];
            float2 as = *(const float2*)&g_asrc[s * 2];
            float e0 = as.x + ad0, e1 = as.y + ad1;
            e0 = e0 > 0.f ? e0 : NEG * e0;
            e1 = e1 > 0.f ? e1 : NEG * e1;
            w0 = __expf(e0); w1 = __expf(e1);
        }
        sh_s[wid][lane] = s; sh_w0[wid][lane] = w0; sh_w1[wid][lane] = w1;
        __syncwarp();

        int nthis = deg - base; if (nthis > 32) nthis = 32;
        int nproc = (nthis + 7) & ~7;
        const float* whp = head ? sh_w1[wid] : sh_w0[wid];
        for (int j = 0; j < nproc; j += 8) {
            int se[8]; float we[8];
            #pragma unroll
            for (int p = 0; p < 8; p++) { se[p] = sh_s[wid][j + p]; we[p] = whp[j + p]; }
            uint2 r[8];
            #pragma unroll
            for (int p = 0; p < 8; p++)
                r[p] = *(const uint2*)&g_hh[(size_t)se[p] * HC + lane * 4];
            #pragma unroll
            for (int p = 0; p < 8; p++) {
                float2 f01 = __half22float2(*(__half2*)&r[p].x);
                float2 f23 = __half22float2(*(__half2*)&r[p].y);
                den  += we[p];
                acc0 += f01.x * we[p]; acc1 += f01.y * we[p];
                acc2 += f23.x * we[p]; acc3 += f23.y * we[p];
            }
        }
        __syncwarp();
    }

    float inv = 1.f / (den + 1e-16f);
    float4 bv = *(const float4*)&bias[lane * 4];
    float v0 = fmaxf(acc0 * inv + bv.x, 0.f);
    float v1 = fmaxf(acc1 * inv + bv.y, 0.f);
    float v2 = fmaxf(acc2 * inv + bv.z, 0.f);
    float v3 = fmaxf(acc3 * inv + bv.w, 0.f);

    float fa[NCLS];
    int k0 = lane * 4;
    #pragma unroll
    for (int c = 0; c < NCLS; c++) {
        const float* wr = &wt[c * HC + k0];
        fa[c] = v0 * wr[0] + v1 * wr[1] + v2 * wr[2] + v3 * wr[3];
    }
    #pragma unroll
    for (int c = 0; c < NCLS; c++)
        #pragma unroll
        for (int o = 16; o; o >>= 1) fa[c] += __shfl_xor_sync(0xffffffffu, fa[c], o);

    if (lane == 0) {
        float mx = -CUDART_INF_F;
        #pragma unroll
        for (int c = 0; c < NCLS; c++) { fa[c] += bfc[c]; mx = fmaxf(mx, fa[c]); }
        float se = 0.f;
        #pragma unroll
        for (int c = 0; c < NCLS; c++) se += __expf(fa[c] - mx);
        float lse = mx + logf(se);
        #pragma unroll
        for (int c = 0; c < NCLS; c++) out[(size_t)node * NCLS + c] = fa[c] - lse;
    }
}

// ---------------- launch ----------------------------------------------------
extern "C" void kernel_launch(void* const* d_in, const int* in_sizes, int n_in,
                              void* d_out, int out_size) {
    const float* x       = (const float*)d_in[0];
    const void*  ei      = d_in[1];
    const float* W       = (const float*)d_in[2];
    const float* att_src = (const float*)d_in[3];
    const float* att_dst = (const float*)d_in[4];
    const float* bias    = (const float*)d_in[5];
    const float* Wfc     = (const float*)d_in[6];
    const float* bfc     = (const float*)d_in[7];
    float* out = (float*)d_out;

    k_init<<<(NNODES + 255) / 256, 256>>>(ei);
    k_gemm_count<<<GEMM_BLKS + CNT_BLKS, 256>>>(x, W, att_src, att_dst, ei);
    k_alloc<<<(NNODES + 255) / 256, 256>>>();
    k_fill<<<(ETOT + 255) / 256, 256>>>();
    k_agg<<<(NNODES + WPB - 1) / WPB, 256>>>(bias, Wfc, bfc, out);
}